// round 1
// baseline (speedup 1.0000x reference)
#include <cuda_runtime.h>
#include <cuda_bf16.h>
#include <math.h>

// Problem constants (validated against setup_inputs shapes)
#define B_   8
#define C_   128
#define H_   128
#define W_   128
#define HW_  16384   // H_*W_
#define NH_  8

// ---------------------------------------------------------------------------
// Scratch (static __device__ arrays — the sanctioned allocation-free path)
// ---------------------------------------------------------------------------
__device__ float g_t  [(size_t)B_ * 384 * HW_];   // pos-conv output t        (201 MB)
__device__ float g_qkv[(size_t)B_ * 384 * HW_];   // qkv (q:0..127,k:128..255,v:256..383)
__device__ float g_y  [(size_t)B_ * 256 * HW_];   // [out(128) | d3(64) | d5(64)]
__device__ float g_Sp [(size_t)B_ * NH_ * 16 * 256]; // partial Gram sums per n-chunk
__device__ float g_qss[(size_t)B_ * 128];         // sum q^2 per (b, h*16+d)
__device__ float g_kss[(size_t)B_ * 128];
__device__ float g_att[(size_t)B_ * NH_ * 16 * 16];

// ---------------------------------------------------------------------------
// Kernel 1/8: SGEMM with optional bias.  Y[b][m][n] = sum_k W[m][k]*X[b][k][n] (+bias[m])
// BM=BN=128, BK=16, 256 threads, 8x8 register tile, double-buffered smem.
// Requires M%128==0, N%128==0, K%16==0 (holds: 384/128 x 128/256 x 16384).
// ---------------------------------------------------------------------------
#define GBM 128
#define GBN 128
#define GBK 16

__global__ void __launch_bounds__(256, 2)
sgemm_bias_kernel(const float* __restrict__ W, const float* __restrict__ X,
                  const float* __restrict__ bias, float* __restrict__ Y,
                  int M, int K, int N)
{
    __shared__ float As[2][GBK][GBM + 4];   // +4 pad: keeps float4 align (528B rows), fewer store conflicts
    __shared__ float Bs[2][GBK][GBN];

    const int b  = blockIdx.z;
    const int m0 = blockIdx.y * GBM;
    const int n0 = blockIdx.x * GBN;
    const float* Xb = X + (size_t)b * K * N + n0;
    float*       Yb = Y + (size_t)b * M * N;

    const int tid = threadIdx.x;
    // A tile loads: 128x16 floats = 512 float4; thread loads rows (tid>>2) and (tid>>2)+64
    const int am0 = tid >> 2;
    const int akk = (tid & 3) * 4;
    // B tile loads: 16x128 floats = 512 float4; rows (tid>>5) and (tid>>5)+8
    const int bk0 = tid >> 5;
    const int bn  = (tid & 31) * 4;

    const int tm = (tid >> 4) * 8;
    const int tn = (tid & 15) * 8;

    float acc[8][8];
    #pragma unroll
    for (int i = 0; i < 8; ++i)
        #pragma unroll
        for (int j = 0; j < 8; ++j) acc[i][j] = 0.f;

    // preload tile 0
    float4 a0 = *(const float4*)(W  + (size_t)(m0 + am0)      * K + akk);
    float4 a1 = *(const float4*)(W  + (size_t)(m0 + am0 + 64) * K + akk);
    float4 b0 = *(const float4*)(Xb + (size_t)bk0       * N + bn);
    float4 b1 = *(const float4*)(Xb + (size_t)(bk0 + 8) * N + bn);
    As[0][akk + 0][am0] = a0.x; As[0][akk + 1][am0] = a0.y;
    As[0][akk + 2][am0] = a0.z; As[0][akk + 3][am0] = a0.w;
    As[0][akk + 0][am0 + 64] = a1.x; As[0][akk + 1][am0 + 64] = a1.y;
    As[0][akk + 2][am0 + 64] = a1.z; As[0][akk + 3][am0 + 64] = a1.w;
    *(float4*)&Bs[0][bk0][bn]     = b0;
    *(float4*)&Bs[0][bk0 + 8][bn] = b1;
    __syncthreads();

    const int ntiles = K / GBK;
    for (int t = 0; t < ntiles; ++t) {
        const int cur = t & 1;
        if (t + 1 < ntiles) {
            const int k0 = (t + 1) * GBK;
            a0 = *(const float4*)(W  + (size_t)(m0 + am0)      * K + k0 + akk);
            a1 = *(const float4*)(W  + (size_t)(m0 + am0 + 64) * K + k0 + akk);
            b0 = *(const float4*)(Xb + (size_t)(k0 + bk0)      * N + bn);
            b1 = *(const float4*)(Xb + (size_t)(k0 + bk0 + 8)  * N + bn);
        }
        #pragma unroll
        for (int kk = 0; kk < GBK; ++kk) {
            float4 ar0 = *(const float4*)&As[cur][kk][tm];
            float4 ar1 = *(const float4*)&As[cur][kk][tm + 4];
            float4 br0 = *(const float4*)&Bs[cur][kk][tn];
            float4 br1 = *(const float4*)&Bs[cur][kk][tn + 4];
            float ar[8] = {ar0.x, ar0.y, ar0.z, ar0.w, ar1.x, ar1.y, ar1.z, ar1.w};
            float br[8] = {br0.x, br0.y, br0.z, br0.w, br1.x, br1.y, br1.z, br1.w};
            #pragma unroll
            for (int i = 0; i < 8; ++i)
                #pragma unroll
                for (int j = 0; j < 8; ++j)
                    acc[i][j] += ar[i] * br[j];
        }
        if (t + 1 < ntiles) {
            const int nxt = cur ^ 1;
            As[nxt][akk + 0][am0] = a0.x; As[nxt][akk + 1][am0] = a0.y;
            As[nxt][akk + 2][am0] = a0.z; As[nxt][akk + 3][am0] = a0.w;
            As[nxt][akk + 0][am0 + 64] = a1.x; As[nxt][akk + 1][am0 + 64] = a1.y;
            As[nxt][akk + 2][am0 + 64] = a1.z; As[nxt][akk + 3][am0 + 64] = a1.w;
            *(float4*)&Bs[nxt][bk0][bn]     = b0;
            *(float4*)&Bs[nxt][bk0 + 8][bn] = b1;
        }
        __syncthreads();
    }

    #pragma unroll
    for (int i = 0; i < 8; ++i) {
        const int m = m0 + tm + i;
        const float bv = bias ? bias[m] : 0.f;
        float* row = Yb + (size_t)m * N + n0 + tn;
        float4 o0 = make_float4(acc[i][0] + bv, acc[i][1] + bv, acc[i][2] + bv, acc[i][3] + bv);
        float4 o1 = make_float4(acc[i][4] + bv, acc[i][5] + bv, acc[i][6] + bv, acc[i][7] + bv);
        *(float4*)(row)     = o0;
        *(float4*)(row + 4) = o1;
    }
}

// ---------------------------------------------------------------------------
// Kernel 2/7: dual grouped conv (3x3 pad1 + 5x5 pad2 in one pass).
// Group og reads input channel pair (2og, 2og+1); writes out channel
// ch3off+og (3x3) and ch5off+og (5x5).  32x32 spatial tile, halo 2.
// ---------------------------------------------------------------------------
#define CT 32

__global__ void __launch_bounds__(256)
dualconv_kernel(const float* __restrict__ in, int inChans,
                const float* __restrict__ w3, const float* __restrict__ b3,
                const float* __restrict__ w5, const float* __restrict__ b5,
                float* __restrict__ out, int outChans, int ch3off, int ch5off)
{
    const int b    = blockIdx.z;
    const int og   = blockIdx.y;
    const int tile = blockIdx.x;              // 0..15
    const int ty0  = (tile >> 2) * CT;
    const int tx0  = (tile & 3)  * CT;

    __shared__ float s[2][CT + 4][CT + 4];    // 2 x 36 x 36
    __shared__ float w3s[2][9], w5s[2][25], bsh[2];

    const int tid = threadIdx.x;
    const float* inb = in + ((size_t)b * inChans + og * 2) * HW_;

    for (int idx = tid; idx < 2 * 36 * 36; idx += 256) {
        const int c  = idx / 1296;
        const int r  = (idx - c * 1296) / 36;
        const int cc = idx - c * 1296 - r * 36;
        const int y  = ty0 + r - 2;
        const int x  = tx0 + cc - 2;
        float v = 0.f;
        if ((unsigned)y < (unsigned)H_ && (unsigned)x < (unsigned)W_)
            v = inb[(size_t)c * HW_ + y * W_ + x];
        s[c][r][cc] = v;
    }
    if (tid < 18)       w3s[tid / 9][tid % 9] = w3[og * 18 + tid];
    else if (tid < 68)  { int j = tid - 18; w5s[j / 25][j % 25] = w5[og * 50 + j]; }
    else if (tid == 68) bsh[0] = b3[og];
    else if (tid == 69) bsh[1] = b5[og];
    __syncthreads();

    float* out3 = out + ((size_t)b * outChans + ch3off + og) * HW_;
    float* out5 = out + ((size_t)b * outChans + ch5off + og) * HW_;

    const int px = tid & 31;
    #pragma unroll
    for (int step = 0; step < 4; ++step) {
        const int py = (tid >> 5) + step * 8;
        float a3 = bsh[0], a5 = bsh[1];
        #pragma unroll
        for (int c = 0; c < 2; ++c) {
            #pragma unroll
            for (int ky = 0; ky < 5; ++ky) {
                #pragma unroll
                for (int kx = 0; kx < 5; ++kx) {
                    const float v = s[c][py + ky][px + kx];
                    a5 += v * w5s[c][ky * 5 + kx];
                    if (ky >= 1 && ky <= 3 && kx >= 1 && kx <= 3)
                        a3 += v * w3s[c][(ky - 1) * 3 + (kx - 1)];
                }
            }
        }
        out3[(ty0 + py) * W_ + tx0 + px] = a3;
        out5[(ty0 + py) * W_ + tx0 + px] = a5;
    }
}

// ---------------------------------------------------------------------------
// Kernel 3: per-(b,channel) sum of squares for q (ch 0..127) and k (128..255)
// ---------------------------------------------------------------------------
__global__ void __launch_bounds__(256)
norm_kernel(const float* __restrict__ qkv, float* __restrict__ qss, float* __restrict__ kss)
{
    const int b  = blockIdx.y;
    const int ch = blockIdx.x;                // 0..255
    const float4* p4 = (const float4*)(qkv + ((size_t)b * 384 + ch) * HW_);
    float s = 0.f;
    for (int i = threadIdx.x; i < HW_ / 4; i += 256) {
        float4 v = p4[i];
        s += v.x * v.x + v.y * v.y + v.z * v.z + v.w * v.w;
    }
    #pragma unroll
    for (int o = 16; o; o >>= 1) s += __shfl_xor_sync(0xffffffffu, s, o);
    __shared__ float ws[8];
    if ((threadIdx.x & 31) == 0) ws[threadIdx.x >> 5] = s;
    __syncthreads();
    if (threadIdx.x == 0) {
        float t = 0.f;
        #pragma unroll
        for (int w = 0; w < 8; ++w) t += ws[w];
        if (ch < 128) qss[b * 128 + ch]       = t;
        else          kss[b * 128 + ch - 128] = t;
    }
}

// ---------------------------------------------------------------------------
// Kernel 4: Gram partials S[b,h,d,e] over an n-chunk of 1024.
// 256 threads = 16 (4x4 subtile position) x 16 column groups; deterministic
// shfl-butterfly reduce across the 16 column groups (no float atomics).
// ---------------------------------------------------------------------------
__global__ void __launch_bounds__(256)
qk_dot_kernel(const float* __restrict__ qkv, float* __restrict__ Sp)
{
    const int b = blockIdx.z, h = blockIdx.y, chunk = blockIdx.x;  // chunk 0..15
    const int n0 = chunk * 1024;
    const float* q  = qkv + ((size_t)b * 384 + h * 16) * HW_ + n0;
    const float* kk = q + 128 * HW_;

    const int tid = threadIdx.x;
    const int cg  = tid & 15;          // column group (fast within warp -> coalesced)
    const int sub = tid >> 4;          // 4x4 subtile id
    const int dB  = (sub >> 2) * 4;
    const int eB  = (sub & 3)  * 4;

    float acc[4][4];
    #pragma unroll
    for (int r = 0; r < 4; ++r)
        #pragma unroll
        for (int c = 0; c < 4; ++c) acc[r][c] = 0.f;

    for (int i = 0; i < 64; ++i) {
        const int col = i * 16 + cg;
        float qa[4], ka[4];
        #pragma unroll
        for (int r = 0; r < 4; ++r) {
            qa[r] = q [(size_t)(dB + r) * HW_ + col];
            ka[r] = kk[(size_t)(eB + r) * HW_ + col];
        }
        #pragma unroll
        for (int r = 0; r < 4; ++r)
            #pragma unroll
            for (int c = 0; c < 4; ++c)
                acc[r][c] += qa[r] * ka[c];
    }

    // reduce over the 16 column groups (lanes tid&15) — deterministic butterfly
    #pragma unroll
    for (int r = 0; r < 4; ++r)
        #pragma unroll
        for (int c = 0; c < 4; ++c) {
            float v = acc[r][c];
            v += __shfl_xor_sync(0xffffffffu, v, 8);
            v += __shfl_xor_sync(0xffffffffu, v, 4);
            v += __shfl_xor_sync(0xffffffffu, v, 2);
            v += __shfl_xor_sync(0xffffffffu, v, 1);
            acc[r][c] = v;
        }

    if (cg == 0) {
        float* dst = Sp + ((size_t)(b * NH_ + h) * 16 + chunk) * 256;
        #pragma unroll
        for (int r = 0; r < 4; ++r)
            #pragma unroll
            for (int c = 0; c < 4; ++c)
                dst[(dB + r) * 16 + (eB + c)] = acc[r][c];
    }
}

// ---------------------------------------------------------------------------
// Kernel 5: reduce chunk partials, apply l2-norm scaling + temp, softmax over e
// ---------------------------------------------------------------------------
__global__ void __launch_bounds__(1024)
softmax_kernel(const float* __restrict__ Sp, const float* __restrict__ qss,
               const float* __restrict__ kss, const float* __restrict__ temp,
               float* __restrict__ attn)
{
    const int tid = threadIdx.x;           // 0..1023 = (b, h, d)
    const int b = tid >> 7, h = (tid >> 4) & 7, d = tid & 15;
    const int bh = b * NH_ + h;

    float row[16];
    #pragma unroll
    for (int e = 0; e < 16; ++e) {
        float s = 0.f;
        #pragma unroll
        for (int c = 0; c < 16; ++c)
            s += Sp[((size_t)bh * 16 + c) * 256 + d * 16 + e];
        row[e] = s;
    }
    const float rq = 1.f / fmaxf(sqrtf(qss[bh * 16 + d]), 1e-12f);
    const float tp = temp[h];
    float mx = -3.4e38f;
    #pragma unroll
    for (int e = 0; e < 16; ++e) {
        const float rk = 1.f / fmaxf(sqrtf(kss[bh * 16 + e]), 1e-12f);
        row[e] *= rq * rk * tp;
        mx = fmaxf(mx, row[e]);
    }
    float sum = 0.f;
    #pragma unroll
    for (int e = 0; e < 16; ++e) { row[e] = expf(row[e] - mx); sum += row[e]; }
    const float inv = 1.f / sum;
    #pragma unroll
    for (int e = 0; e < 16; ++e)
        attn[((size_t)bh * 16 + d) * 16 + e] = row[e] * inv;
}

// ---------------------------------------------------------------------------
// Kernel 6: out[b, h*16+d, n] = sum_e attn[b,h,d,e] * v[b,h,e,n]  -> y[0:128]
// ---------------------------------------------------------------------------
__global__ void __launch_bounds__(256)
av_kernel(const float* __restrict__ qkv, const float* __restrict__ attn, float* __restrict__ y)
{
    const int b = blockIdx.z, h = blockIdx.y;
    __shared__ float a[16][16];
    a[threadIdx.x >> 4][threadIdx.x & 15] = attn[(size_t)(b * NH_ + h) * 256 + threadIdx.x];
    __syncthreads();

    const float* v = qkv + ((size_t)b * 384 + 256 + h * 16) * HW_;
    float*       o = y   + ((size_t)b * 256 + h * 16) * HW_;
    const int n = blockIdx.x * 256 + threadIdx.x;   // gridDim.x = 64 -> covers HW_

    float vv[16];
    #pragma unroll
    for (int e = 0; e < 16; ++e) vv[e] = v[(size_t)e * HW_ + n];
    #pragma unroll
    for (int d = 0; d < 16; ++d) {
        float s = 0.f;
        #pragma unroll
        for (int e = 0; e < 16; ++e) s += a[d][e] * vv[e];
        o[(size_t)d * HW_ + n] = s;
    }
}

// ---------------------------------------------------------------------------
// Launch
// ---------------------------------------------------------------------------
extern "C" void kernel_launch(void* const* d_in, const int* in_sizes, int n_in,
                              void* d_out, int out_size)
{
    const float* x      = (const float*)d_in[0];
    const float* pos_w  = (const float*)d_in[1];
    const float* pos_b  = (const float*)d_in[2];
    const float* qd3_w  = (const float*)d_in[3];
    const float* qd3_b  = (const float*)d_in[4];
    const float* qd5_w  = (const float*)d_in[5];
    const float* qd5_b  = (const float*)d_in[6];
    const float* temp   = (const float*)d_in[7];
    const float* d3_w   = (const float*)d_in[8];
    const float* d3_b   = (const float*)d_in[9];
    const float* d5_w   = (const float*)d_in[10];
    const float* d5_b   = (const float*)d_in[11];
    const float* proj_w = (const float*)d_in[12];

    float *t, *qkv, *y, *Sp, *qss, *kss, *att;
    cudaGetSymbolAddress((void**)&t,   g_t);
    cudaGetSymbolAddress((void**)&qkv, g_qkv);
    cudaGetSymbolAddress((void**)&y,   g_y);
    cudaGetSymbolAddress((void**)&Sp,  g_Sp);
    cudaGetSymbolAddress((void**)&qss, g_qss);
    cudaGetSymbolAddress((void**)&kss, g_kss);
    cudaGetSymbolAddress((void**)&att, g_att);

    // 1. t = pos 1x1 conv (SGEMM M=384,K=128 + bias)
    sgemm_bias_kernel<<<dim3(HW_ / GBN, 384 / GBM, B_), 256>>>(pos_w, x, pos_b, t, 384, 128, HW_);
    // 2. qkv = [qd3(t) | qd5(t)]  (grouped dual conv)
    dualconv_kernel<<<dim3(16, 192, B_), 256>>>(t, 384, qd3_w, qd3_b, qd5_w, qd5_b, qkv, 384, 0, 192);
    // 3. l2-norm sums for q,k
    norm_kernel<<<dim3(256, B_), 256>>>(qkv, qss, kss);
    // 4. Gram matrix partials
    qk_dot_kernel<<<dim3(16, NH_, B_), 256>>>(qkv, Sp);
    // 5. scale + softmax
    softmax_kernel<<<1, 1024>>>(Sp, qss, kss, temp, att);
    // 6. y[0:128] = attn @ v
    av_kernel<<<dim3(64, NH_, B_), 256>>>(qkv, att, y);
    // 7. y[128:256] = [d3(x) | d5(x)]
    dualconv_kernel<<<dim3(16, 64, B_), 256>>>(x, 128, d3_w, d3_b, d5_w, d5_b, y, 256, 128, 192);
    // 8. final = proj 1x1 conv (SGEMM M=128,K=256, no bias)
    sgemm_bias_kernel<<<dim3(HW_ / GBN, 128 / GBM, B_), 256>>>(proj_w, y, nullptr, (float*)d_out, 128, 256, HW_);
}

// round 3
// speedup vs baseline: 1.0814x; 1.0814x over previous
#include <cuda_runtime.h>
#include <cuda_bf16.h>
#include <math.h>

#define B_   8
#define C_   128
#define H_   128
#define W_   128
#define HW_  16384
#define NH_  8

// ---------------------------------------------------------------------------
// Scratch
// ---------------------------------------------------------------------------
__device__ float g_t   [(size_t)B_ * 384 * HW_];
__device__ float g_qkv [(size_t)B_ * 384 * HW_];
__device__ float g_y   [(size_t)B_ * 256 * HW_];
__device__ float g_Sp  [(size_t)B_ * NH_ * 16 * 256];
__device__ float g_qssp[(size_t)B_ * NH_ * 16 * 16];
__device__ float g_kssp[(size_t)B_ * NH_ * 16 * 16];
__device__ float g_att [(size_t)B_ * NH_ * 16 * 16];

// ---------------------------------------------------------------------------
// Packed fp32x2 helpers (PTX ISA 8.6+, sm_100+: full-rate fp32 path; scalar
// 3-reg FFMA is half-rate on Blackwell)
// ---------------------------------------------------------------------------
typedef unsigned long long u64;
__device__ __forceinline__ u64 pk2(float lo, float hi) {
    u64 r; asm("mov.b64 %0, {%1, %2};" : "=l"(r) : "f"(lo), "f"(hi)); return r;
}
__device__ __forceinline__ void fma2(u64& d, u64 a, u64 b) {
    asm("fma.rn.f32x2 %0, %1, %2, %0;" : "+l"(d) : "l"(a), "l"(b));
}
__device__ __forceinline__ float2 up2(u64 v) {
    float2 f; asm("mov.b64 {%0, %1}, %2;" : "=f"(f.x), "=f"(f.y) : "l"(v)); return f;
}

// ---------------------------------------------------------------------------
// SGEMM (1x1 conv): Y[b][m][n] = sum_k W[m][k] * X[b][k][n] (+ bias[m])
// 128x128x16 tiles, 256 thr, 8x8 per-thread tile held as 8x4 f32x2 pairs.
// ---------------------------------------------------------------------------
#define GBM 128
#define GBN 128
#define GBK 16

__global__ void __launch_bounds__(256, 2)
sgemm_bias_kernel(const float* __restrict__ W, const float* __restrict__ X,
                  const float* __restrict__ bias, float* __restrict__ Y,
                  int M, int K, int N)
{
    __shared__ float As[2][GBK][GBM + 4];
    __shared__ float Bs[2][GBK][GBN];

    const int b  = blockIdx.z;
    const int m0 = blockIdx.y * GBM;
    const int n0 = blockIdx.x * GBN;
    const float* Xb = X + (size_t)b * K * N + n0;
    float*       Yb = Y + (size_t)b * M * N;

    const int tid = threadIdx.x;
    const int am0 = tid >> 2;
    const int akk = (tid & 3) * 4;
    const int bk0 = tid >> 5;
    const int bn  = (tid & 31) * 4;
    const int tm  = (tid >> 4) * 8;
    const int tn  = (tid & 15) * 8;

    u64 acc[8][4];
    #pragma unroll
    for (int i = 0; i < 8; ++i)
        #pragma unroll
        for (int j = 0; j < 4; ++j) acc[i][j] = 0ull;

    float4 a0 = *(const float4*)(W  + (size_t)(m0 + am0)      * K + akk);
    float4 a1 = *(const float4*)(W  + (size_t)(m0 + am0 + 64) * K + akk);
    float4 b0 = *(const float4*)(Xb + (size_t)bk0       * N + bn);
    float4 b1 = *(const float4*)(Xb + (size_t)(bk0 + 8) * N + bn);
    As[0][akk + 0][am0] = a0.x; As[0][akk + 1][am0] = a0.y;
    As[0][akk + 2][am0] = a0.z; As[0][akk + 3][am0] = a0.w;
    As[0][akk + 0][am0 + 64] = a1.x; As[0][akk + 1][am0 + 64] = a1.y;
    As[0][akk + 2][am0 + 64] = a1.z; As[0][akk + 3][am0 + 64] = a1.w;
    *(float4*)&Bs[0][bk0][bn]     = b0;
    *(float4*)&Bs[0][bk0 + 8][bn] = b1;
    __syncthreads();

    const int ntiles = K / GBK;
    for (int t = 0; t < ntiles; ++t) {
        const int cur = t & 1;
        if (t + 1 < ntiles) {
            const int k0 = (t + 1) * GBK;
            a0 = *(const float4*)(W  + (size_t)(m0 + am0)      * K + k0 + akk);
            a1 = *(const float4*)(W  + (size_t)(m0 + am0 + 64) * K + k0 + akk);
            b0 = *(const float4*)(Xb + (size_t)(k0 + bk0)      * N + bn);
            b1 = *(const float4*)(Xb + (size_t)(k0 + bk0 + 8)  * N + bn);
        }
        #pragma unroll
        for (int kk = 0; kk < GBK; ++kk) {
            float4 ar0 = *(const float4*)&As[cur][kk][tm];
            float4 ar1 = *(const float4*)&As[cur][kk][tm + 4];
            const u64* brow = (const u64*)&Bs[cur][kk][tn];
            u64 bb0 = brow[0], bb1 = brow[1], bb2 = brow[2], bb3 = brow[3];
            float ar[8] = {ar0.x, ar0.y, ar0.z, ar0.w, ar1.x, ar1.y, ar1.z, ar1.w};
            #pragma unroll
            for (int i = 0; i < 8; ++i) {
                u64 a2 = pk2(ar[i], ar[i]);
                fma2(acc[i][0], a2, bb0);
                fma2(acc[i][1], a2, bb1);
                fma2(acc[i][2], a2, bb2);
                fma2(acc[i][3], a2, bb3);
            }
        }
        if (t + 1 < ntiles) {
            const int nxt = cur ^ 1;
            As[nxt][akk + 0][am0] = a0.x; As[nxt][akk + 1][am0] = a0.y;
            As[nxt][akk + 2][am0] = a0.z; As[nxt][akk + 3][am0] = a0.w;
            As[nxt][akk + 0][am0 + 64] = a1.x; As[nxt][akk + 1][am0 + 64] = a1.y;
            As[nxt][akk + 2][am0 + 64] = a1.z; As[nxt][akk + 3][am0 + 64] = a1.w;
            *(float4*)&Bs[nxt][bk0][bn]     = b0;
            *(float4*)&Bs[nxt][bk0 + 8][bn] = b1;
        }
        __syncthreads();
    }

    #pragma unroll
    for (int i = 0; i < 8; ++i) {
        const int m = m0 + tm + i;
        const float bv = bias ? bias[m] : 0.f;
        float2 c0 = up2(acc[i][0]), c1 = up2(acc[i][1]);
        float2 c2 = up2(acc[i][2]), c3 = up2(acc[i][3]);
        float* row = Yb + (size_t)m * N + n0 + tn;
        *(float4*)(row)     = make_float4(c0.x + bv, c0.y + bv, c1.x + bv, c1.y + bv);
        *(float4*)(row + 4) = make_float4(c2.x + bv, c2.y + bv, c3.x + bv, c3.y + bv);
    }
}

// ---------------------------------------------------------------------------
// Dual grouped conv (3x3 pad1 + 5x5 pad2), group og reads channels (2og,2og+1)
// ---------------------------------------------------------------------------
#define CT 32

__global__ void __launch_bounds__(256)
dualconv_kernel(const float* __restrict__ in, int inChans,
                const float* __restrict__ w3, const float* __restrict__ b3,
                const float* __restrict__ w5, const float* __restrict__ b5,
                float* __restrict__ out, int outChans, int ch3off, int ch5off)
{
    const int b    = blockIdx.z;
    const int og   = blockIdx.y;
    const int tile = blockIdx.x;
    const int ty0  = (tile >> 2) * CT;
    const int tx0  = (tile & 3)  * CT;

    __shared__ float s[2][CT + 4][CT + 4];
    __shared__ float w3s[2][9], w5s[2][25], bsh[2];

    const int tid = threadIdx.x;
    const float* inb = in + ((size_t)b * inChans + og * 2) * HW_;

    for (int idx = tid; idx < 2 * 36 * 36; idx += 256) {
        const int c  = idx / 1296;
        const int r  = (idx - c * 1296) / 36;
        const int cc = idx - c * 1296 - r * 36;
        const int y  = ty0 + r - 2;
        const int x  = tx0 + cc - 2;
        float v = 0.f;
        if ((unsigned)y < (unsigned)H_ && (unsigned)x < (unsigned)W_)
            v = inb[(size_t)c * HW_ + y * W_ + x];
        s[c][r][cc] = v;
    }
    if (tid < 18)       w3s[tid / 9][tid % 9] = w3[og * 18 + tid];
    else if (tid < 68)  { int j = tid - 18; w5s[j / 25][j % 25] = w5[og * 50 + j]; }
    else if (tid == 68) bsh[0] = b3[og];
    else if (tid == 69) bsh[1] = b5[og];
    __syncthreads();

    float* out3 = out + ((size_t)b * outChans + ch3off + og) * HW_;
    float* out5 = out + ((size_t)b * outChans + ch5off + og) * HW_;

    const int px = tid & 31;
    #pragma unroll
    for (int step = 0; step < 4; ++step) {
        const int py = (tid >> 5) + step * 8;
        float a3 = bsh[0], a5 = bsh[1];
        #pragma unroll
        for (int c = 0; c < 2; ++c) {
            #pragma unroll
            for (int ky = 0; ky < 5; ++ky) {
                #pragma unroll
                for (int kx = 0; kx < 5; ++kx) {
                    const float v = s[c][py + ky][px + kx];
                    a5 += v * w5s[c][ky * 5 + kx];
                    if (ky >= 1 && ky <= 3 && kx >= 1 && kx <= 3)
                        a3 += v * w3s[c][(ky - 1) * 3 + (kx - 1)];
                }
            }
        }
        out3[(ty0 + py) * W_ + tx0 + px] = a3;
        out5[(ty0 + py) * W_ + tx0 + px] = a5;
    }
}

// ---------------------------------------------------------------------------
// Gram partials + fused sum-of-squares.  float4 loads.
// Thread = (sub 4x4-subtile, cg column-group).  1024 cols/chunk, 16 chunks.
// ---------------------------------------------------------------------------
__global__ void __launch_bounds__(256)
qk_dot_kernel(const float* __restrict__ qkv, float* __restrict__ Sp,
              float* __restrict__ qssp, float* __restrict__ kssp)
{
    const int b = blockIdx.z, h = blockIdx.y, chunk = blockIdx.x;
    const int n0 = chunk * 1024;
    const float* qb = qkv + ((size_t)b * 384 + h * 16) * HW_ + n0;
    const float* kb = qb + 128 * HW_;

    const int tid = threadIdx.x;
    const int cg  = tid & 15;
    const int sub = tid >> 4;
    const int dB  = (sub >> 2) * 4;
    const int eB  = (sub & 3)  * 4;

    const float4* q4[4];
    const float4* k4[4];
    #pragma unroll
    for (int r = 0; r < 4; ++r) {
        q4[r] = (const float4*)(qb + (size_t)(dB + r) * HW_);
        k4[r] = (const float4*)(kb + (size_t)(eB + r) * HW_);
    }

    float acc[4][4];
    float qs[4] = {0.f, 0.f, 0.f, 0.f};
    float ks[4] = {0.f, 0.f, 0.f, 0.f};
    #pragma unroll
    for (int r = 0; r < 4; ++r)
        #pragma unroll
        for (int c = 0; c < 4; ++c) acc[r][c] = 0.f;

    #pragma unroll 4
    for (int i = 0; i < 16; ++i) {
        const int idx = i * 16 + cg;
        float4 qa[4], ka[4];
        #pragma unroll
        for (int r = 0; r < 4; ++r) { qa[r] = q4[r][idx]; ka[r] = k4[r][idx]; }
        #pragma unroll
        for (int r = 0; r < 4; ++r)
            #pragma unroll
            for (int c = 0; c < 4; ++c)
                acc[r][c] += qa[r].x * ka[c].x + qa[r].y * ka[c].y
                           + qa[r].z * ka[c].z + qa[r].w * ka[c].w;
        if (eB == 0) {
            #pragma unroll
            for (int r = 0; r < 4; ++r)
                qs[r] += qa[r].x * qa[r].x + qa[r].y * qa[r].y
                       + qa[r].z * qa[r].z + qa[r].w * qa[r].w;
        }
        if (dB == 0) {
            #pragma unroll
            for (int c = 0; c < 4; ++c)
                ks[c] += ka[c].x * ka[c].x + ka[c].y * ka[c].y
                       + ka[c].z * ka[c].z + ka[c].w * ka[c].w;
        }
    }

    // deterministic butterfly over the 16 column groups (lane bits 0..3)
    #pragma unroll
    for (int r = 0; r < 4; ++r)
        #pragma unroll
        for (int c = 0; c < 4; ++c) {
            float v = acc[r][c];
            v += __shfl_xor_sync(0xffffffffu, v, 8);
            v += __shfl_xor_sync(0xffffffffu, v, 4);
            v += __shfl_xor_sync(0xffffffffu, v, 2);
            v += __shfl_xor_sync(0xffffffffu, v, 1);
            acc[r][c] = v;
        }
    #pragma unroll
    for (int r = 0; r < 4; ++r) {
        float v = qs[r], w = ks[r];
        v += __shfl_xor_sync(0xffffffffu, v, 8); w += __shfl_xor_sync(0xffffffffu, w, 8);
        v += __shfl_xor_sync(0xffffffffu, v, 4); w += __shfl_xor_sync(0xffffffffu, w, 4);
        v += __shfl_xor_sync(0xffffffffu, v, 2); w += __shfl_xor_sync(0xffffffffu, w, 2);
        v += __shfl_xor_sync(0xffffffffu, v, 1); w += __shfl_xor_sync(0xffffffffu, w, 1);
        qs[r] = v; ks[r] = w;
    }

    const int bh = b * NH_ + h;
    if (cg == 0) {
        float* dst = Sp + ((size_t)bh * 16 + chunk) * 256;
        #pragma unroll
        for (int r = 0; r < 4; ++r)
            #pragma unroll
            for (int c = 0; c < 4; ++c)
                dst[(dB + r) * 16 + (eB + c)] = acc[r][c];
        if (eB == 0) {
            #pragma unroll
            for (int r = 0; r < 4; ++r)
                qssp[((size_t)bh * 16 + chunk) * 16 + dB + r] = qs[r];
        }
        if (dB == 0) {
            #pragma unroll
            for (int c = 0; c < 4; ++c)
                kssp[((size_t)bh * 16 + chunk) * 16 + eB + c] = ks[c];
        }
    }
}

// ---------------------------------------------------------------------------
// Reduce chunk partials, l2-norm scaling + temp, softmax over e
// ---------------------------------------------------------------------------
__global__ void __launch_bounds__(1024)
softmax_kernel(const float* __restrict__ Sp, const float* __restrict__ qssp,
               const float* __restrict__ kssp, const float* __restrict__ temp,
               float* __restrict__ attn)
{
    const int tid = threadIdx.x;
    const int b = tid >> 7, h = (tid >> 4) & 7, d = tid & 15;
    const int bh = b * NH_ + h;

    __shared__ float kssS[64][16];

    float sq = 0.f, sk = 0.f;
    #pragma unroll
    for (int c = 0; c < 16; ++c) {
        sq += qssp[((size_t)bh * 16 + c) * 16 + d];
        sk += kssp[((size_t)bh * 16 + c) * 16 + d];
    }
    kssS[bh][d] = sk;
    __syncthreads();

    float row[16];
    #pragma unroll
    for (int e = 0; e < 16; ++e) {
        float s = 0.f;
        #pragma unroll
        for (int c = 0; c < 16; ++c)
            s += Sp[((size_t)bh * 16 + c) * 256 + d * 16 + e];
        row[e] = s;
    }
    const float rq = 1.f / fmaxf(sqrtf(sq), 1e-12f);
    const float tp = temp[h];
    float mx = -3.4e38f;
    #pragma unroll
    for (int e = 0; e < 16; ++e) {
        const float rk = 1.f / fmaxf(sqrtf(kssS[bh][e]), 1e-12f);
        row[e] *= rq * rk * tp;
        mx = fmaxf(mx, row[e]);
    }
    float sum = 0.f;
    #pragma unroll
    for (int e = 0; e < 16; ++e) { row[e] = expf(row[e] - mx); sum += row[e]; }
    const float inv = 1.f / sum;
    #pragma unroll
    for (int e = 0; e < 16; ++e)
        attn[((size_t)bh * 16 + d) * 16 + e] = row[e] * inv;
}

// ---------------------------------------------------------------------------
// out[b, h*16+d, n..n+3] = sum_e attn[d,e] * v[e, n..n+3]   (float4, MLP=16)
// ---------------------------------------------------------------------------
__global__ void __launch_bounds__(256)
av_kernel(const float* __restrict__ qkv, const float* __restrict__ attn, float* __restrict__ y)
{
    const int b = blockIdx.z, h = blockIdx.y;
    __shared__ float a[16][16];
    a[threadIdx.x >> 4][threadIdx.x & 15] = attn[(size_t)(b * NH_ + h) * 256 + threadIdx.x];
    __syncthreads();

    const float4* v = (const float4*)(qkv + ((size_t)b * 384 + 256 + h * 16) * HW_);
    float4*       o = (float4*)(y + ((size_t)b * 256 + h * 16) * HW_);
    const int n4 = blockIdx.x * 256 + threadIdx.x;   // gridDim.x = 16 -> covers HW_/4

    float4 vv[16];
    #pragma unroll
    for (int e = 0; e < 16; ++e) vv[e] = v[(size_t)e * (HW_ / 4) + n4];
    #pragma unroll
    for (int d = 0; d < 16; ++d) {
        float sx = 0.f, sy = 0.f, sz = 0.f, sw = 0.f;
        #pragma unroll
        for (int e = 0; e < 16; ++e) {
            const float w = a[d][e];
            sx += w * vv[e].x; sy += w * vv[e].y;
            sz += w * vv[e].z; sw += w * vv[e].w;
        }
        o[(size_t)d * (HW_ / 4) + n4] = make_float4(sx, sy, sz, sw);
    }
}

// ---------------------------------------------------------------------------
// Launch
// ---------------------------------------------------------------------------
extern "C" void kernel_launch(void* const* d_in, const int* in_sizes, int n_in,
                              void* d_out, int out_size)
{
    const float* x      = (const float*)d_in[0];
    const float* pos_w  = (const float*)d_in[1];
    const float* pos_b  = (const float*)d_in[2];
    const float* qd3_w  = (const float*)d_in[3];
    const float* qd3_b  = (const float*)d_in[4];
    const float* qd5_w  = (const float*)d_in[5];
    const float* qd5_b  = (const float*)d_in[6];
    const float* temp   = (const float*)d_in[7];
    const float* d3_w   = (const float*)d_in[8];
    const float* d3_b   = (const float*)d_in[9];
    const float* d5_w   = (const float*)d_in[10];
    const float* d5_b   = (const float*)d_in[11];
    const float* proj_w = (const float*)d_in[12];

    float *t, *qkv, *y, *Sp, *qssp, *kssp, *att;
    cudaGetSymbolAddress((void**)&t,    g_t);
    cudaGetSymbolAddress((void**)&qkv,  g_qkv);
    cudaGetSymbolAddress((void**)&y,    g_y);
    cudaGetSymbolAddress((void**)&Sp,   g_Sp);
    cudaGetSymbolAddress((void**)&qssp, g_qssp);
    cudaGetSymbolAddress((void**)&kssp, g_kssp);
    cudaGetSymbolAddress((void**)&att,  g_att);

    sgemm_bias_kernel<<<dim3(HW_ / GBN, 384 / GBM, B_), 256>>>(pos_w, x, pos_b, t, 384, 128, HW_);
    dualconv_kernel<<<dim3(16, 192, B_), 256>>>(t, 384, qd3_w, qd3_b, qd5_w, qd5_b, qkv, 384, 0, 192);
    qk_dot_kernel<<<dim3(16, NH_, B_), 256>>>(qkv, Sp, qssp, kssp);
    softmax_kernel<<<1, 1024>>>(Sp, qssp, kssp, temp, att);
    av_kernel<<<dim3(16, NH_, B_), 256>>>(qkv, att, y);
    dualconv_kernel<<<dim3(16, 64, B_), 256>>>(x, 128, d3_w, d3_b, d5_w, d5_b, y, 256, 128, 192);
    sgemm_bias_kernel<<<dim3(HW_ / GBN, 128 / GBM, B_), 256>>>(proj_w, y, nullptr, (float*)d_out, 128, 256, HW_);
}